// round 12
// baseline (speedup 1.0000x reference)
#include <cuda_runtime.h>
#include <cuda_fp16.h>

// FFM layer: out[b] = sigmoid( linear(b) + 0.5*sum_k((sum_g f)^2 - sum_g f^2) )
// f[b,g,k] = sum_d dense_x[b,d]*v[d,g,k] + sum_i v[idx[b,i],g,k]
//
// Inputs: d_in[0] dense_x f32[B,13], d_in[1] sparse_x i32[B,26],
//         d_in[2] W f32[26013], d_in[3] b f32[1], d_in[4] v f32[26013,39,8]
// Output: f32 [B]
//
// R12: prep kernel (fused) converts v -> fp16 table AND precomputes the dense
// matvec dense_f[b] = dense_x[b] @ v[:13] (fp32 accum, rounded once to fp16,
// stored in gather-row layout). Main kernel is a pure 27-row fp16 gather-add
// (1 dense row + 26 sparse rows) with no smem and no FFMA block, so its load
// stream can saturate the LTS chip cap (~6300 B/cyc).

namespace {
constexpr int N_DENSE  = 13;
constexpr int N_SPARSE = 26;
constexpr int ONEHOT   = 1000;
constexpr int FIELDS   = 39;
constexpr int ROWF     = FIELDS * 8;                   // 312 floats per row
constexpr int ROWH4    = FIELDS;                       // 39 uint4 per fp16 row
constexpr int ROW4     = ROWF / 4;                     // 78 float4 per fp32 row
constexpr int N_ROWS   = N_DENSE + N_SPARSE * ONEHOT;  // 26013
constexpr int TOT      = N_ROWS * ROWF;                // 8,116,056 halves
constexpr int B_MAX    = 16384;
constexpr int SPB      = 8;                            // warps (samples) per block
constexpr int THREADS  = 256;

constexpr int CVT_N      = TOT / 8;                    // uint4 outputs
constexpr int CVT_BLOCKS = (CVT_N + 255) / 256;        // 3964
}

__device__ __align__(16) __half g_vh[TOT];             // 16.2 MB fp16 table
__device__ __align__(16) __half g_df[B_MAX * ROWF];    // 10.2 MB dense_f rows

__device__ __forceinline__ __half2 u2h2(unsigned u) {
    __half2 h; *reinterpret_cast<unsigned*>(&h) = u; return h;
}

// ---------------------------------------------------------------- prep -----
// Blocks [0, CVT_BLOCKS): convert v fp32 -> fp16 table.
// Blocks [CVT_BLOCKS, ...): dense_f matvec, one warp per sample.
__global__ void __launch_bounds__(THREADS) prep_kernel(
    const float4* __restrict__ v4,
    const float*  __restrict__ dense_x,
    int B)
{
    if (blockIdx.x < CVT_BLOCKS) {
        int i = blockIdx.x * THREADS + threadIdx.x;
        if (i >= CVT_N) return;
        float4 a = __ldg(v4 + 2 * i);
        float4 b = __ldg(v4 + 2 * i + 1);
        __half2 h0 = __floats2half2_rn(a.x, a.y);
        __half2 h1 = __floats2half2_rn(a.z, a.w);
        __half2 h2 = __floats2half2_rn(b.x, b.y);
        __half2 h3 = __floats2half2_rn(b.z, b.w);
        uint4 o;
        o.x = *reinterpret_cast<unsigned*>(&h0);
        o.y = *reinterpret_cast<unsigned*>(&h1);
        o.z = *reinterpret_cast<unsigned*>(&h2);
        o.w = *reinterpret_cast<unsigned*>(&h3);
        reinterpret_cast<uint4*>(g_vh)[i] = o;
        return;
    }

    // ---- dense_f part ----
    __shared__ float4 s_vd[N_DENSE * ROW4];            // v[:13] fp32, swizzled
    const int tid  = threadIdx.x;
    const int lane = tid & 31;
    const int b    = (blockIdx.x - CVT_BLOCKS) * SPB + (tid >> 5);

    #pragma unroll
    for (int j = tid; j < N_DENSE * ROW4; j += THREADS) {
        int s = j % ROW4;
        int phys = s ^ ((s >> 3) & 1);
        s_vd[(j / ROW4) * ROW4 + phys] = __ldg(v4 + j);
    }
    __syncthreads();
    if (b >= B) return;

    float dxr = (lane < N_DENSE) ? dense_x[b * N_DENSE + lane] : 0.0f;
    const bool hasB = (lane < FIELDS - 32);            // lane < 7

    const int jA0 = 2 * lane,      jA1 = 2 * lane + 1;
    const int jB0 = 64 + 2 * lane, jB1 = 65 + 2 * lane;
    const int pA0 = jA0 ^ ((jA0 >> 3) & 1), pA1 = jA1 ^ ((jA1 >> 3) & 1);
    const int pB0 = jB0 ^ ((jB0 >> 3) & 1), pB1 = jB1 ^ ((jB1 >> 3) & 1);

    float fA[8] = {0,0,0,0,0,0,0,0}, fB[8] = {0,0,0,0,0,0,0,0};
    #pragma unroll
    for (int d = 0; d < N_DENSE; ++d) {
        const float xd = __shfl_sync(0xffffffffu, dxr, d);
        const float4* row = &s_vd[d * ROW4];
        float4 t0 = row[pA0], t1 = row[pA1];
        fA[0] = fmaf(xd, t0.x, fA[0]); fA[1] = fmaf(xd, t0.y, fA[1]);
        fA[2] = fmaf(xd, t0.z, fA[2]); fA[3] = fmaf(xd, t0.w, fA[3]);
        fA[4] = fmaf(xd, t1.x, fA[4]); fA[5] = fmaf(xd, t1.y, fA[5]);
        fA[6] = fmaf(xd, t1.z, fA[6]); fA[7] = fmaf(xd, t1.w, fA[7]);
        if (hasB) {
            float4 t2 = row[pB0], t3 = row[pB1];
            fB[0] = fmaf(xd, t2.x, fB[0]); fB[1] = fmaf(xd, t2.y, fB[1]);
            fB[2] = fmaf(xd, t2.z, fB[2]); fB[3] = fmaf(xd, t2.w, fB[3]);
            fB[4] = fmaf(xd, t3.x, fB[4]); fB[5] = fmaf(xd, t3.y, fB[5]);
            fB[6] = fmaf(xd, t3.z, fB[6]); fB[7] = fmaf(xd, t3.w, fB[7]);
        }
    }

    uint4* out4 = reinterpret_cast<uint4*>(g_df) + (size_t)b * ROWH4;
    {
        __half2 h0 = __floats2half2_rn(fA[0], fA[1]);
        __half2 h1 = __floats2half2_rn(fA[2], fA[3]);
        __half2 h2 = __floats2half2_rn(fA[4], fA[5]);
        __half2 h3 = __floats2half2_rn(fA[6], fA[7]);
        uint4 o;
        o.x = *reinterpret_cast<unsigned*>(&h0);
        o.y = *reinterpret_cast<unsigned*>(&h1);
        o.z = *reinterpret_cast<unsigned*>(&h2);
        o.w = *reinterpret_cast<unsigned*>(&h3);
        out4[lane] = o;
    }
    if (hasB) {
        __half2 h0 = __floats2half2_rn(fB[0], fB[1]);
        __half2 h1 = __floats2half2_rn(fB[2], fB[3]);
        __half2 h2 = __floats2half2_rn(fB[4], fB[5]);
        __half2 h3 = __floats2half2_rn(fB[6], fB[7]);
        uint4 o;
        o.x = *reinterpret_cast<unsigned*>(&h0);
        o.y = *reinterpret_cast<unsigned*>(&h1);
        o.z = *reinterpret_cast<unsigned*>(&h2);
        o.w = *reinterpret_cast<unsigned*>(&h3);
        out4[32 + lane] = o;
    }
}

// ---------------------------------------------------------------- main -----
__global__ __launch_bounds__(THREADS) void ffm_kernel(
    const float* __restrict__ dense_x,
    const int*   __restrict__ sparse_x,
    const float* __restrict__ W,
    const float* __restrict__ bias,
    float*       __restrict__ out,
    int B)
{
    const int tid  = threadIdx.x;
    const int lane = tid & 31;
    const int b    = blockIdx.x * SPB + (tid >> 5);
    const bool valid = (b < B);
    const bool hasB  = (lane < FIELDS - 32);           // lane < 7

    float dxr  = (valid && lane < N_DENSE) ? dense_x[b * N_DENSE + lane] : 0.0f;
    int   idxr = (valid && lane < N_SPARSE)
               ? (N_DENSE + lane * ONEHOT + sparse_x[b * N_SPARSE + lane])
               : N_DENSE;

    // Two alternating half2 accumulation chains per field.
    __half2 cA[2][4], cB[2][4];
    #pragma unroll
    for (int c = 0; c < 2; ++c)
        #pragma unroll
        for (int m = 0; m < 4; ++m) {
            cA[c][m] = __floats2half2_rn(0.0f, 0.0f);
            cB[c][m] = __floats2half2_rn(0.0f, 0.0f);
        }

    // Row 0: precomputed dense_f (same layout as a gather row).
    {
        const uint4* dr = reinterpret_cast<const uint4*>(g_df)
                        + (size_t)(valid ? b : 0) * ROWH4;
        uint4 hA = __ldg(dr + lane);
        cA[0][0] = u2h2(hA.x); cA[0][1] = u2h2(hA.y);
        cA[0][2] = u2h2(hA.z); cA[0][3] = u2h2(hA.w);
        if (hasB) {
            uint4 hB = __ldg(dr + 32 + lane);
            cB[0][0] = u2h2(hB.x); cB[0][1] = u2h2(hB.y);
            cB[0][2] = u2h2(hB.z); cB[0][3] = u2h2(hB.w);
        }
    }

    // Rows 1..26: sparse gathers.
    const uint4* vh4 = reinterpret_cast<const uint4*>(g_vh);
    #pragma unroll
    for (int i = 0; i < N_SPARSE; ++i) {
        const int r = __shfl_sync(0xffffffffu, idxr, i);
        const uint4* rp = vh4 + (size_t)r * ROWH4;
        const int c = i & 1;
        uint4 hA = __ldg(rp + lane);
        cA[c][0] = __hadd2(cA[c][0], u2h2(hA.x));
        cA[c][1] = __hadd2(cA[c][1], u2h2(hA.y));
        cA[c][2] = __hadd2(cA[c][2], u2h2(hA.z));
        cA[c][3] = __hadd2(cA[c][3], u2h2(hA.w));
        if (hasB) {
            uint4 hB = __ldg(rp + 32 + lane);
            cB[c][0] = __hadd2(cB[c][0], u2h2(hB.x));
            cB[c][1] = __hadd2(cB[c][1], u2h2(hB.y));
            cB[c][2] = __hadd2(cB[c][2], u2h2(hB.z));
            cB[c][3] = __hadd2(cB[c][3], u2h2(hB.w));
        }
    }

    // Merge chains to fp32 per-field vectors.
    float fA[8], fB[8];
    #pragma unroll
    for (int m = 0; m < 4; ++m) {
        float2 a0 = __half22float2(cA[0][m]);
        float2 a1 = __half22float2(cA[1][m]);
        fA[2 * m]     = a0.x + a1.x;
        fA[2 * m + 1] = a0.y + a1.y;
        float2 b0 = __half22float2(cB[0][m]);
        float2 b1 = __half22float2(cB[1][m]);
        fB[2 * m]     = b0.x + b1.x;
        fB[2 * m + 1] = b0.y + b1.y;
    }

    // Epilogue (fp32).
    float s[8], q = 0.0f;
    #pragma unroll
    for (int k = 0; k < 8; ++k) {
        s[k] = fA[k] + fB[k];
        q = fmaf(fA[k], fA[k], q);
        q = fmaf(fB[k], fB[k], q);
    }

    float lin = 0.0f;
    if (lane < N_SPARSE) lin = __ldg(W + idxr);
    if (lane < N_DENSE)  lin = fmaf(dxr, __ldg(W + lane), lin);

    #pragma unroll
    for (int m = 16; m >= 1; m >>= 1) {
        q   += __shfl_xor_sync(0xffffffffu, q, m);
        lin += __shfl_xor_sync(0xffffffffu, lin, m);
    }
    #pragma unroll
    for (int k = 0; k < 8; ++k)
        #pragma unroll
        for (int m = 16; m >= 1; m >>= 1)
            s[k] += __shfl_xor_sync(0xffffffffu, s[k], m);

    float ss = 0.0f;
    #pragma unroll
    for (int k = 0; k < 8; ++k) ss = fmaf(s[k], s[k], ss);

    if (lane == 0 && valid) {
        float z = lin + 0.5f * (ss - q) + __ldg(bias);
        out[b] = 1.0f / (1.0f + expf(-z));
    }
}

extern "C" void kernel_launch(void* const* d_in, const int* in_sizes, int n_in,
                              void* d_out, int out_size)
{
    const float* dense_x  = (const float*)d_in[0];
    const int*   sparse_x = (const int*)  d_in[1];
    const float* W        = (const float*)d_in[2];
    const float* bias     = (const float*)d_in[3];
    const float* v        = (const float*)d_in[4];
    float*       out      = (float*)d_out;

    const int B = in_sizes[0] / N_DENSE;
    const int dense_blocks = (B + SPB - 1) / SPB;

    prep_kernel<<<CVT_BLOCKS + dense_blocks, THREADS>>>(
        reinterpret_cast<const float4*>(v), dense_x, B);

    ffm_kernel<<<(B + SPB - 1) / SPB, THREADS>>>(
        dense_x, sparse_x, W, bias, out, B);
}